// round 1
// baseline (speedup 1.0000x reference)
#include <cuda_runtime.h>
#include <math_constants.h>

#define N 512
#define NTHREADS 512

// 512x512 cost matrix in double (2 MB) — static device scratch (no allocs).
__device__ double g_cost[N * N];

__global__ void __launch_bounds__(NTHREADS, 1)
tofu_jv_kernel(const float* __restrict__ dgm,
               const float* __restrict__ dgm_x,
               float* __restrict__ out)
{
    const int t = threadIdx.x;      // 0..511, handles column j = t+1 (1-indexed)
    const int j = t + 1;

    __shared__ double s_u[N + 1];
    __shared__ double s_v[N + 1];
    __shared__ double s_minv[N + 1];
    __shared__ int    s_p[N + 1];      // p[j] = row matched to column j (1-indexed)
    __shared__ int    s_way[N + 1];
    __shared__ int    s_used[N + 1];
    __shared__ int    s_j0;
    __shared__ int    s_i0;
    __shared__ double s_delta;
    __shared__ int    s_j1;
    __shared__ int    s_done;
    __shared__ double s_red_val[16];
    __shared__ int    s_red_idx[16];

    // ---------------------------------------------------------------
    // Phase 0: cost matrix in IEEE double, no FMA contraction, to match
    // numpy float64: sqrt((b-bx)^2 + (d-dx)^2) with plain mul/add.
    // Thread t owns column t; loop over rows -> coalesced stores.
    // ---------------------------------------------------------------
    {
        const double xb = (double)dgm_x[2 * t];
        const double xd = (double)dgm_x[2 * t + 1];
        #pragma unroll 4
        for (int i = 0; i < N; i++) {
            const double b  = (double)dgm[2 * i];
            const double d  = (double)dgm[2 * i + 1];
            const double db = __dsub_rn(b, xb);
            const double dd = __dsub_rn(d, xd);
            const double ss = __dadd_rn(__dmul_rn(db, db), __dmul_rn(dd, dd));
            g_cost[i * N + t] = sqrt(ss);
        }
    }

    // init duals / matching
    for (int k = t; k <= N; k += NTHREADS) {
        s_u[k] = 0.0;
        s_v[k] = 0.0;
        s_p[k] = 0;
    }
    __syncthreads();

    // ---------------------------------------------------------------
    // Phase 1: Jonker–Volgenant shortest augmenting paths, one row at a time.
    // ---------------------------------------------------------------
    for (int i = 1; i <= N; i++) {
        // per-row init
        s_minv[j] = CUDART_INF;
        s_used[j] = 0;
        if (t == 0) {
            s_p[0]    = i;
            s_j0      = 0;
            s_used[0] = 0;
            s_minv[0] = CUDART_INF;
        }
        __syncthreads();

        while (true) {
            // mark j0 used, fetch its row
            if (t == 0) {
                s_used[s_j0] = 1;
                s_i0 = s_p[s_j0];
            }
            __syncthreads();

            const int    j0loc = s_j0;
            const int    i0    = s_i0;
            const double u_i0  = s_u[i0];

            // relax column j (if free) and produce argmin candidate
            double val;
            if (!s_used[j]) {
                // cur = cost - u[i0] - v[j]  (left-assoc, matches numpy)
                double cur = __dsub_rn(__dsub_rn(g_cost[(i0 - 1) * N + t], u_i0), s_v[j]);
                if (cur < s_minv[j]) {
                    s_minv[j] = cur;
                    s_way[j]  = j0loc;
                }
                val = s_minv[j];
            } else {
                val = CUDART_INF;
            }
            int idx = j;

            // warp-level (min val, smallest idx on tie) reduction
            #pragma unroll
            for (int off = 16; off > 0; off >>= 1) {
                double ov = __shfl_down_sync(0xffffffffu, val, off);
                int    oi = __shfl_down_sync(0xffffffffu, idx, off);
                if (ov < val || (ov == val && oi < idx)) { val = ov; idx = oi; }
            }
            const int w = t >> 5;
            if ((t & 31) == 0) { s_red_val[w] = val; s_red_idx[w] = idx; }
            __syncthreads();

            if (w == 0) {
                val = (t < 16) ? s_red_val[t] : CUDART_INF;
                idx = (t < 16) ? s_red_idx[t] : 0x7fffffff;
                #pragma unroll
                for (int off = 8; off > 0; off >>= 1) {
                    double ov = __shfl_down_sync(0xffffffffu, val, off);
                    int    oi = __shfl_down_sync(0xffffffffu, idx, off);
                    if (ov < val || (ov == val && oi < idx)) { val = ov; idx = oi; }
                }
                if (t == 0) { s_delta = val; s_j1 = idx; }
            }
            __syncthreads();

            const double delta = s_delta;
            // dual updates: used cols (incl. j0): u[p[j]] += delta, v[j] -= delta
            // free cols: minv[j] -= delta.  p[j] distinct over used j -> race-free.
            if (s_used[j]) {
                s_u[s_p[j]] = __dadd_rn(s_u[s_p[j]], delta);
                s_v[j]      = __dsub_rn(s_v[j], delta);
            } else {
                s_minv[j]   = __dsub_rn(s_minv[j], delta);
            }
            if (t == 0) {
                // column 0 is always used: p[0] = i
                s_u[s_p[0]] = __dadd_rn(s_u[s_p[0]], delta);
                s_v[0]      = __dsub_rn(s_v[0], delta);
                s_j0   = s_j1;
                s_done = (s_p[s_j1] == 0);
            }
            __syncthreads();
            if (s_done) break;
        }

        // augment along way[] (short serial chain)
        if (t == 0) {
            int j0 = s_j0;
            while (j0) {
                int j1 = s_way[j0];
                s_p[j0] = s_p[j1];
                j0 = j1;
            }
        }
        __syncthreads();
    }

    // ---------------------------------------------------------------
    // Phase 2: loss = 0.5 * sum_i || dgm[i] - dgm_x[sigma(i)] ||^2.
    // Thread t handles column j: row = p[j]-1 is matched to col j-1.
    // ---------------------------------------------------------------
    {
        const int row = s_p[j] - 1;
        const int col = j - 1;
        const double db = (double)dgm[2 * row]     - (double)dgm_x[2 * col];
        const double dd = (double)dgm[2 * row + 1] - (double)dgm_x[2 * col + 1];
        double acc = db * db + dd * dd;

        #pragma unroll
        for (int off = 16; off > 0; off >>= 1)
            acc += __shfl_down_sync(0xffffffffu, acc, off);
        if ((t & 31) == 0) s_red_val[t >> 5] = acc;
        __syncthreads();
        if (t < 16) {
            acc = s_red_val[t];
            #pragma unroll
            for (int off = 8; off > 0; off >>= 1)
                acc += __shfl_down_sync(0x0000ffffu, acc, off);
            if (t == 0) out[0] = (float)(0.5 * acc);
        }
    }
}

extern "C" void kernel_launch(void* const* d_in, const int* in_sizes, int n_in,
                              void* d_out, int out_size)
{
    const float* dgm   = (const float*)d_in[0];
    const float* dgm_x = (const float*)d_in[1];
    float* out = (float*)d_out;
    tofu_jv_kernel<<<1, NTHREADS>>>(dgm, dgm_x, out);
}

// round 3
// speedup vs baseline: 2.2419x; 2.2419x over previous
#include <cuda_runtime.h>
#include <math_constants.h>

#define N  512
#define NT 512
#define FULLMASK 0xffffffffu

// 512x512 cost matrix in double (2 MB) — static device scratch (no allocs).
__device__ double g_cost[N * N];

// Monotone bijection: double -> u64 with a < b  <=>  key(a) < key(b).
__device__ __forceinline__ unsigned long long mono_key(double x) {
    long long b = __double_as_longlong(x);
    unsigned long long u = (unsigned long long)b;
    return (b < 0) ? ~u : (u | 0x8000000000000000ULL);
}
__device__ __forceinline__ double inv_mono_key(unsigned long long k) {
    long long b = (k & 0x8000000000000000ULL)
                ? (long long)(k & 0x7fffffffffffffffULL)
                : (long long)~k;
    return __longlong_as_double(b);
}

__global__ void __launch_bounds__(NT, 1)
tofu_lap_kernel(const float* __restrict__ dgm,
                const float* __restrict__ dgm_x,
                float* __restrict__ out)
{
    const int t = threadIdx.x;   // owns column j = t (0-indexed)
    const int w = t >> 5;

    __shared__ double s_u[N];                       // row duals
    __shared__ int    s_p[N];                       // col -> matched row, -1 if free
    __shared__ int    s_way[N];                     // Dijkstra parents (temp: row flags)
    __shared__ int    s_argmin[N];
    __shared__ int    s_freerows[N];
    __shared__ int    s_nfree;
    __shared__ unsigned long long s_wkey[2][16];    // double-buffered warp partials
    __shared__ int    s_widx[2][16];
    __shared__ double s_red[16];

    // ---------------------------------------------------------------
    // Phase 0: cost matrix in IEEE double (matches numpy float64:
    // plain mul/add, no FMA contraction, IEEE sqrt). Coalesced stores.
    // ---------------------------------------------------------------
    {
        const double xb = (double)dgm_x[2 * t];
        const double xd = (double)dgm_x[2 * t + 1];
        #pragma unroll 4
        for (int i = 0; i < N; i++) {
            const double b  = (double)dgm[2 * i];
            const double d  = (double)dgm[2 * i + 1];
            const double db = __dsub_rn(b, xb);
            const double dd = __dsub_rn(d, xd);
            g_cost[i * N + t] = sqrt(__dadd_rn(__dmul_rn(db, db), __dmul_rn(dd, dd)));
        }
        s_u[t]   = 0.0;
        s_way[t] = 0;     // temp: row-claimed flags for column reduction
    }
    __syncthreads();

    // ---------------------------------------------------------------
    // Phase 1a: column reduction. v[j] = min_i cost[i][j] in a REGISTER.
    // Greedy pre-matching of unique argmin rows (dual-feasible, tight).
    // ---------------------------------------------------------------
    double v;
    {
        double vmin = g_cost[t];
        int    amin = 0;
        for (int i = 1; i < N; i++) {
            double c = g_cost[i * N + t];
            if (c < vmin) { vmin = c; amin = i; }
        }
        v = vmin;
        s_argmin[t] = amin;
    }
    __syncthreads();
    if (t == 0) {
        for (int jj = 0; jj < N; jj++) {
            int r = s_argmin[jj];
            if (!s_way[r]) { s_way[r] = 1; s_p[jj] = r; }
            else           { s_p[jj] = -1; }
        }
        int cnt = 0;
        for (int i = 0; i < N; i++)
            if (!s_way[i]) s_freerows[cnt++] = i;
        s_nfree = cnt;
    }
    __syncthreads();
    const int nfree = s_nfree;

    // ---------------------------------------------------------------
    // Phase 1b: LAPJV shortest augmenting paths (absolute distances).
    // Candidate dist through j0:  dist[j0] + (c[i0][j] - u[i0] - v[j]).
    // Duals frozen during a search; all updates deferred to the end.
    // One __syncthreads per Dijkstra step.
    // ---------------------------------------------------------------
    int pb = 0;
    for (int k = 0; k < nfree; k++) {
        const int iFree = s_freerows[k];

        double dist  = CUDART_INF;
        double dJ0   = 0.0;                  // dist of current tree column (virtual=0)
        double distF = 0.0;
        int    way   = -1;
        bool   used  = false;
        int    j0    = -1;
        int    i0    = iFree;
        double c     = g_cost[i0 * N + t];   // prefetch first row

        while (true) {
            const double u0 = s_u[i0];       // frozen during this search

            if (!used) {
                double cand = __dadd_rn(dJ0,
                               __dsub_rn(__dsub_rn(c, u0), v));
                if (cand < dist) { dist = cand; way = j0; }
            }

            // exact (min dist, min idx) via 3x REDUX on monotone key
            unsigned long long key = used ? ~0ULL : mono_key(dist);
            unsigned hi = (unsigned)(key >> 32);
            unsigned lo = (unsigned)key;
            unsigned whi  = __reduce_min_sync(FULLMASK, hi);
            unsigned wlo  = __reduce_min_sync(FULLMASK, (hi == whi) ? lo : 0xffffffffu);
            unsigned widx = __reduce_min_sync(FULLMASK,
                                (hi == whi && lo == wlo) ? (unsigned)t : 0xffffffffu);
            if ((unsigned)t == widx) { s_wkey[pb][w] = key; s_widx[pb][w] = t; }
            __syncthreads();                 // the ONLY barrier per step

            unsigned long long bk = s_wkey[pb][0];
            int                bi = s_widx[pb][0];
            #pragma unroll
            for (int q = 1; q < 16; q++) {
                unsigned long long kk = s_wkey[pb][q];
                int                ii = s_widx[pb][q];
                if (kk < bk || (kk == bk && ii < bi)) { bk = kk; bi = ii; }
            }
            const int j1 = bi;
            pb ^= 1;

            dJ0   = inv_mono_key(bk);        // dist[j1], recovered by ALL threads
            distF = dJ0;

            const int pj1 = s_p[j1];
            if (t == j1) {
                used = true;
                s_way[j1] = way;
            }
            j0 = j1;
            if (pj1 < 0) break;              // reached a free column

            i0 = pj1;
            c  = g_cost[i0 * N + t];         // prefetch next row
        }
        __syncthreads();                     // s_way visible; pre-augment snapshot

        // deferred dual updates (use OLD p, before augmentation)
        if (used) {
            const double dd = __dsub_rn(distF, dist);
            v = __dsub_rn(v, dd);
            const int pj = s_p[t];
            if (pj >= 0) s_u[pj] = __dadd_rn(s_u[pj], dd);  // rows distinct -> race-free
        }
        if (t == 0) s_u[iFree] = __dadd_rn(s_u[iFree], distF);
        __syncthreads();                     // duals done before p changes

        if (t == 0) {                        // augment along parent chain
            int jc = j0;
            while (true) {
                int jp = s_way[jc];
                s_p[jc] = (jp < 0) ? iFree : s_p[jp];
                if (jp < 0) break;
                jc = jp;
            }
        }
        __syncthreads();
    }

    // ---------------------------------------------------------------
    // Phase 2: loss = 0.5 * sum_j || dgm[p[j]] - dgm_x[j] ||^2
    // ---------------------------------------------------------------
    {
        const int row = s_p[t];
        const double db = (double)dgm[2 * row]     - (double)dgm_x[2 * t];
        const double dd = (double)dgm[2 * row + 1] - (double)dgm_x[2 * t + 1];
        double acc = db * db + dd * dd;

        #pragma unroll
        for (int off = 16; off > 0; off >>= 1)
            acc += __shfl_down_sync(FULLMASK, acc, off);
        if ((t & 31) == 0) s_red[w] = acc;
        __syncthreads();
        if (t < 16) {
            acc = s_red[t];
            #pragma unroll
            for (int off = 8; off > 0; off >>= 1)
                acc += __shfl_down_sync(0x0000ffffu, acc, off);
            if (t == 0) out[0] = (float)(0.5 * acc);
        }
    }
}

extern "C" void kernel_launch(void* const* d_in, const int* in_sizes, int n_in,
                              void* d_out, int out_size)
{
    const float* dgm   = (const float*)d_in[0];
    const float* dgm_x = (const float*)d_in[1];
    float* out = (float*)d_out;
    tofu_lap_kernel<<<1, NT>>>(dgm, dgm_x, out);
}

// round 4
// speedup vs baseline: 3.1119x; 1.3881x over previous
#include <cuda_runtime.h>
#include <math_constants.h>

#define N   512
#define NT  256
#define NW  (NT / 32)
#define FULLMASK 0xffffffffu
#define ARR_CAP (3 * N)

typedef unsigned long long ull;

// 512x512 cost matrix in double (2 MB) — static device scratch (no allocs).
__device__ double g_cost[N * N];

// Monotone bijection: double -> u64 with a < b  <=>  key(a) < key(b).
__device__ __forceinline__ ull mono_key(double x) {
    long long b = __double_as_longlong(x);
    ull u = (ull)b;
    return (b < 0) ? ~u : (u | 0x8000000000000000ULL);
}
__device__ __forceinline__ double inv_mono_key(ull k) {
    long long b = (k & 0x8000000000000000ULL) ? (long long)(k & 0x7fffffffffffffffULL)
                                              : (long long)~k;
    return __longlong_as_double(b);
}

// Block-wide exact (min key, an argmin col). All NT threads must call.
// Contains exactly one __syncthreads. Caller double-buffers `slots`.
__device__ __forceinline__ void block_argmin(ull key, int col, ulonglong2* slots,
                                             ull& bk, int& bcol)
{
    const int lane = threadIdx.x & 31;
    const int w    = threadIdx.x >> 5;
    unsigned hi  = (unsigned)(key >> 32);
    unsigned lo  = (unsigned)key;
    unsigned whi = __reduce_min_sync(FULLMASK, hi);
    unsigned wlo = __reduce_min_sync(FULLMASK, (hi == whi) ? lo : 0xffffffffu);
    unsigned msk = __ballot_sync(FULLMASK, (hi == whi) && (lo == wlo));
    if (lane == __ffs(msk) - 1)
        slots[w] = make_ulonglong2(((ull)whi << 32) | wlo, (ull)(unsigned)col);
    __syncthreads();
    ulonglong2 a0 = slots[0], a1 = slots[1], a2 = slots[2], a3 = slots[3];
    ulonglong2 a4 = slots[4], a5 = slots[5], a6 = slots[6], a7 = slots[7];
    if (a4.x < a0.x) a0 = a4;
    if (a5.x < a1.x) a1 = a5;
    if (a6.x < a2.x) a2 = a6;
    if (a7.x < a3.x) a3 = a7;
    if (a2.x < a0.x) a0 = a2;
    if (a3.x < a1.x) a1 = a3;
    if (a1.x < a0.x) a0 = a1;
    bk   = a0.x;
    bcol = (int)(unsigned)a0.y;
}

__global__ void __launch_bounds__(NT, 1)
tofu_lap_kernel(const float* __restrict__ dgm,
                const float* __restrict__ dgm_x,
                float* __restrict__ out)
{
    const int t  = threadIdx.x;       // owns columns c0 = 2t, c1 = 2t+1
    const int c0 = 2 * t, c1 = 2 * t + 1;
    const int w  = t >> 5;

    __shared__ double     s_u[N];          // row duals
    __shared__ int        s_p[N];          // col -> matched row, -1 if free
    __shared__ int        s_way[N];        // Dijkstra parents (temp: CR row flags)
    __shared__ int        s_argmin[N];
    __shared__ int        s_list[2][N];    // ARR ping-pong / final free-row list
    __shared__ ulonglong2 s_slots[2][NW];  // double-buffered reduction slots
    __shared__ int        s_cur_i, s_arr_done, s_final_sel, s_final_cnt;
    __shared__ double     s_red[NW];

    // ---------------------------------------------------------------
    // Phase 0: cost matrix, IEEE double (plain mul/add, no FMA, IEEE
    // sqrt — matches numpy float64). double2 stores, 16B aligned.
    // ---------------------------------------------------------------
    {
        const double xb0 = (double)dgm_x[2 * c0], xd0 = (double)dgm_x[2 * c0 + 1];
        const double xb1 = (double)dgm_x[2 * c1], xd1 = (double)dgm_x[2 * c1 + 1];
        for (int i = 0; i < N; i++) {
            const double b = (double)dgm[2 * i], d = (double)dgm[2 * i + 1];
            double db0 = __dsub_rn(b, xb0), dd0 = __dsub_rn(d, xd0);
            double db1 = __dsub_rn(b, xb1), dd1 = __dsub_rn(d, xd1);
            double2 cc;
            cc.x = sqrt(__dadd_rn(__dmul_rn(db0, db0), __dmul_rn(dd0, dd0)));
            cc.y = sqrt(__dadd_rn(__dmul_rn(db1, db1), __dmul_rn(dd1, dd1)));
            *(double2*)&g_cost[i * N + c0] = cc;
        }
        s_way[c0] = 0; s_way[c1] = 0;      // temp: row-claimed flags for CR
    }
    __syncthreads();

    // ---------------------------------------------------------------
    // Phase 1a: column reduction. v[j] = min_i cost[i][j] in registers.
    // Greedy pre-match of unique argmin rows (tight, feasible).
    // ---------------------------------------------------------------
    double v0, v1;
    {
        double2 vm = *(const double2*)&g_cost[c0];
        int a0 = 0, a1 = 0;
        for (int i = 1; i < N; i++) {
            double2 cc = *(const double2*)&g_cost[i * N + c0];
            if (cc.x < vm.x) { vm.x = cc.x; a0 = i; }
            if (cc.y < vm.y) { vm.y = cc.y; a1 = i; }
        }
        v0 = vm.x; v1 = vm.y;
        s_argmin[c0] = a0; s_argmin[c1] = a1;
    }
    __syncthreads();
    if (t == 0) {
        int cnt = 0;
        for (int jj = 0; jj < N; jj++) {
            int r = s_argmin[jj];
            if (!s_way[r]) { s_way[r] = 1; s_p[jj] = r; }
            else           { s_p[jj] = -1; }
        }
        for (int i = 0; i < N; i++)
            if (!s_way[i]) s_list[0][cnt++] = i;
        if (cnt == 0) { s_arr_done = 1; s_final_sel = 1; s_final_cnt = 0; }
        else          { s_arr_done = 0; s_cur_i = s_list[0][0]; }
        s_argmin[0] = cnt;                 // stash count (reads all done above)
    }
    __syncthreads();

    // ---------------------------------------------------------------
    // Phase 1b: augmenting row reduction (LAPJV), two sweeps + cap.
    // min/secondmin of reduced row cost; v[j1] -= (u2-u1); displacement
    // chains. Exactness-safe: leftover rows go to the Dijkstra phase.
    // ---------------------------------------------------------------
    int pb = 0;
    {
        // t0 driver state (live in t0's registers; harmless elsewhere)
        int kidx = 1, cntIn = s_argmin[0], cntOut = 0;
        int insel = 0, outsel = 1, sweep = 0, iters = 0;

        while (true) {
            if (s_arr_done) break;
            const int i = s_cur_i;
            double2 cc = *(const double2*)&g_cost[i * N + c0];
            double h0 = __dsub_rn(cc.x, v0);
            double h1 = __dsub_rn(cc.y, v1);
            ull k0 = mono_key(h0), k1 = mono_key(h1);

            ull kl; int cl;
            if (k1 < k0) { kl = k1; cl = c1; } else { kl = k0; cl = c0; }
            ull kmin; int j1;
            block_argmin(kl, cl, s_slots[pb], kmin, j1); pb ^= 1;

            ull e0 = (c0 == j1) ? ~0ULL : k0;
            ull e1 = (c1 == j1) ? ~0ULL : k1;
            if (e1 < e0) { kl = e1; cl = c1; } else { kl = e0; cl = c0; }
            ull ksub; int j2;
            block_argmin(kl, cl, s_slots[pb], ksub, j2); pb ^= 1;

            const bool strict = (kmin < ksub);
            if (strict) {
                double dv = __dsub_rn(inv_mono_key(ksub), inv_mono_key(kmin));
                if      (j1 == c0) v0 = __dsub_rn(v0, dv);
                else if (j1 == c1) v1 = __dsub_rn(v1, dv);
            }
            if (t == 0) {
                int jf = j1;
                if (!strict && s_p[j1] >= 0) jf = j2;
                int i0 = s_p[jf];
                s_p[jf] = i;
                iters++;
                int nexti = -1;
                if (i0 >= 0 && strict) {
                    nexti = i0;                         // reprocess displaced row now
                } else {
                    if (i0 >= 0) s_list[outsel][cntOut++] = i0;
                    while (true) {
                        if (kidx < cntIn) { nexti = s_list[insel][kidx++]; break; }
                        if (sweep == 0) {
                            sweep = 1; insel ^= 1; outsel ^= 1;
                            cntIn = cntOut; cntOut = 0; kidx = 0;
                            continue;
                        }
                        break;
                    }
                }
                if (nexti >= 0 && iters >= ARR_CAP) {   // safety dump
                    s_list[outsel][cntOut++] = nexti;
                    while (kidx < cntIn) s_list[outsel][cntOut++] = s_list[insel][kidx++];
                    nexti = -1;
                }
                if (nexti < 0) { s_arr_done = 1; s_final_sel = outsel; s_final_cnt = cntOut; }
                else s_cur_i = nexti;
            }
            __syncthreads();
        }
    }

    // Rebuild row duals from tight matched edges; free rows get u = 0.
    s_u[c0] = 0.0; s_u[c1] = 0.0;
    __syncthreads();
    {
        int r0 = s_p[c0]; if (r0 >= 0) s_u[r0] = __dsub_rn(g_cost[r0 * N + c0], v0);
        int r1 = s_p[c1]; if (r1 >= 0) s_u[r1] = __dsub_rn(g_cost[r1 * N + c1], v1);
    }
    __syncthreads();
    const int fsel = s_final_sel;
    const int fcnt = s_final_cnt;

    // ---------------------------------------------------------------
    // Phase 1c: shortest augmenting paths (absolute distances, duals
    // frozen per search, deferred updates). One barrier per step.
    // ---------------------------------------------------------------
    for (int f = 0; f < fcnt; f++) {
        const int iFree = s_list[fsel][f];

        double dist0 = CUDART_INF, dist1 = CUDART_INF;
        int    way0 = -1, way1 = -1;
        bool   used0 = false, used1 = false;
        double dJ0 = 0.0;
        int    j0 = -1;
        int    i0 = iFree;
        double u0 = s_u[i0];
        double2 cc = *(const double2*)&g_cost[i0 * N + c0];

        while (true) {
            const double sA = __dsub_rn(u0, dJ0);   // cand = c - (sA + v)
            if (!used0) {
                double cand = __dsub_rn(cc.x, __dadd_rn(sA, v0));
                if (cand < dist0) { dist0 = cand; way0 = j0; }
            }
            if (!used1) {
                double cand = __dsub_rn(cc.y, __dadd_rn(sA, v1));
                if (cand < dist1) { dist1 = cand; way1 = j0; }
            }
            ull k0 = used0 ? ~0ULL : mono_key(dist0);
            ull k1 = used1 ? ~0ULL : mono_key(dist1);
            ull kl; int cl;
            if (k1 < k0) { kl = k1; cl = c1; } else { kl = k0; cl = c0; }
            ull bk; int j1;
            block_argmin(kl, cl, s_slots[pb], bk, j1); pb ^= 1;

            dJ0 = inv_mono_key(bk);
            const int pj1 = s_p[j1];
            if      (j1 == c0) { used0 = true; s_way[j1] = way0; }
            else if (j1 == c1) { used1 = true; s_way[j1] = way1; }
            j0 = j1;
            if (pj1 < 0) break;            // reached a free column
            i0 = pj1;
            u0 = s_u[i0];
            cc = *(const double2*)&g_cost[i0 * N + c0];
        }
        __syncthreads();                   // s_way complete; pre-augment snapshot

        const double distF = dJ0;
        if (used0) {
            double dd = __dsub_rn(distF, dist0);
            v0 = __dsub_rn(v0, dd);
            int pj = s_p[c0];
            if (pj >= 0) s_u[pj] = __dadd_rn(s_u[pj], dd);
        }
        if (used1) {
            double dd = __dsub_rn(distF, dist1);
            v1 = __dsub_rn(v1, dd);
            int pj = s_p[c1];
            if (pj >= 0) s_u[pj] = __dadd_rn(s_u[pj], dd);
        }
        if (t == 0) s_u[iFree] = __dadd_rn(s_u[iFree], distF);
        __syncthreads();                   // duals done before p changes

        if (t == 0) {                      // augment along parent chain
            int jc = j0;
            while (true) {
                int jp = s_way[jc];
                s_p[jc] = (jp < 0) ? iFree : s_p[jp];
                if (jp < 0) break;
                jc = jp;
            }
        }
        __syncthreads();
    }

    // ---------------------------------------------------------------
    // Phase 2: loss = 0.5 * sum_j || dgm[p[j]] - dgm_x[j] ||^2
    // ---------------------------------------------------------------
    {
        const int r0 = s_p[c0], r1 = s_p[c1];
        double db = (double)dgm[2 * r0]     - (double)dgm_x[2 * c0];
        double dd = (double)dgm[2 * r0 + 1] - (double)dgm_x[2 * c0 + 1];
        double acc = db * db + dd * dd;
        db = (double)dgm[2 * r1]     - (double)dgm_x[2 * c1];
        dd = (double)dgm[2 * r1 + 1] - (double)dgm_x[2 * c1 + 1];
        acc += db * db + dd * dd;

        #pragma unroll
        for (int off = 16; off > 0; off >>= 1)
            acc += __shfl_down_sync(FULLMASK, acc, off);
        if ((t & 31) == 0) s_red[w] = acc;
        __syncthreads();
        if (t < NW) {
            acc = s_red[t];
            #pragma unroll
            for (int off = NW / 2; off > 0; off >>= 1)
                acc += __shfl_down_sync(0x000000ffu, acc, off);
            if (t == 0) out[0] = (float)(0.5 * acc);
        }
    }
}

extern "C" void kernel_launch(void* const* d_in, const int* in_sizes, int n_in,
                              void* d_out, int out_size)
{
    const float* dgm   = (const float*)d_in[0];
    const float* dgm_x = (const float*)d_in[1];
    float* out = (float*)d_out;
    tofu_lap_kernel<<<1, NT>>>(dgm, dgm_x, out);
}

// round 8
// speedup vs baseline: 3.2745x; 1.0522x over previous
#include <cuda_runtime.h>
#include <math_constants.h>

#define N   512
#define NT  256
#define NW  (NT / 32)
#define FULLMASK 0xffffffffu
#define ARR_CAP (3 * N)
#define KEY_INF 0xffffffffffffffffULL

typedef unsigned long long ull;

// 512x512 cost matrix in double (2 MB) — static device scratch (no allocs).
__device__ double g_cost[N * N];

// Monotone bijection: double -> u64 with a < b  <=>  key(a) < key(b).
__device__ __forceinline__ ull mono_key(double x) {
    long long b = __double_as_longlong(x);
    ull u = (ull)b;
    return (b < 0) ? ~u : (u | 0x8000000000000000ULL);
}
__device__ __forceinline__ double inv_mono_key(ull k) {
    long long b = (k & 0x8000000000000000ULL) ? (long long)(k & 0x7fffffffffffffffULL)
                                              : (long long)~k;
    return __longlong_as_double(b);
}

// Block-wide exact (min key, argmin payload). All NT threads call.
// payload = ((p+1) << 32) | col  (p part optional). One __syncthreads inside;
// caller double-buffers `slots`.
__device__ __forceinline__ void block_argmin(ull key, ull payload, ulonglong2* slots,
                                             ull& bk, ull& bpay)
{
    const int lane = threadIdx.x & 31;
    const int w    = threadIdx.x >> 5;
    unsigned hi  = (unsigned)(key >> 32);
    unsigned lo  = (unsigned)key;
    unsigned whi = __reduce_min_sync(FULLMASK, hi);
    unsigned wlo = __reduce_min_sync(FULLMASK, (hi == whi) ? lo : 0xffffffffu);
    unsigned msk = __ballot_sync(FULLMASK, (hi == whi) && (lo == wlo));
    if (lane == __ffs(msk) - 1)
        slots[w] = make_ulonglong2(key, payload);
    __syncthreads();
    ulonglong2 a0 = slots[0], a1 = slots[1], a2 = slots[2], a3 = slots[3];
    ulonglong2 a4 = slots[4], a5 = slots[5], a6 = slots[6], a7 = slots[7];
    if (a4.x < a0.x) a0 = a4;
    if (a5.x < a1.x) a1 = a5;
    if (a6.x < a2.x) a2 = a6;
    if (a7.x < a3.x) a3 = a7;
    if (a2.x < a0.x) a0 = a2;
    if (a3.x < a1.x) a1 = a3;
    if (a1.x < a0.x) a0 = a1;
    bk   = a0.x;
    bpay = a0.y;
}

__global__ void __launch_bounds__(NT, 1)
tofu_lap_kernel(const float* __restrict__ dgm,
                const float* __restrict__ dgm_x,
                float* __restrict__ out)
{
    const int t  = threadIdx.x;       // owns columns c0 = 2t, c1 = 2t+1
    const int c0 = 2 * t, c1 = 2 * t + 1;
    const int w  = t >> 5;

    __shared__ double     s_u[N];          // row duals
    __shared__ int        s_p[N];          // col -> matched row, -1 if free
    __shared__ int        s_way[N];        // Dijkstra parents (temp: CR row flags)
    __shared__ int        s_xrow[N];       // row -> matched col, -1 (for RT)
    __shared__ int        s_argmin[N];
    __shared__ int        s_list[2][N];    // ARR ping-pong / final free-row list
    __shared__ ulonglong2 s_slots[2][NW];  // double-buffered reduction slots
    __shared__ int        s_cur_i, s_arr_done, s_final_sel, s_final_cnt;
    __shared__ double     s_red[NW];

    // ---------------------------------------------------------------
    // Phase 0: cost matrix, IEEE double (plain mul/add, no FMA, IEEE
    // sqrt — matches numpy float64). double2 stores, 16B aligned.
    // ---------------------------------------------------------------
    {
        const double xb0 = (double)dgm_x[2 * c0], xd0 = (double)dgm_x[2 * c0 + 1];
        const double xb1 = (double)dgm_x[2 * c1], xd1 = (double)dgm_x[2 * c1 + 1];
        for (int i = 0; i < N; i++) {
            const double b = (double)dgm[2 * i], d = (double)dgm[2 * i + 1];
            double db0 = __dsub_rn(b, xb0), dd0 = __dsub_rn(d, xd0);
            double db1 = __dsub_rn(b, xb1), dd1 = __dsub_rn(d, xd1);
            double2 cc;
            cc.x = sqrt(__dadd_rn(__dmul_rn(db0, db0), __dmul_rn(dd0, dd0)));
            cc.y = sqrt(__dadd_rn(__dmul_rn(db1, db1), __dmul_rn(dd1, dd1)));
            *(double2*)&g_cost[i * N + c0] = cc;
        }
        s_way[c0] = 0; s_way[c1] = 0;      // temp: row-claimed flags for CR
    }
    __syncthreads();

    // ---------------------------------------------------------------
    // Phase 1a: column reduction. v[j] = min_i cost[i][j] in registers.
    // Greedy pre-match of unique argmin rows (tight, feasible).
    // ---------------------------------------------------------------
    double v0, v1;
    {
        double2 vm = *(const double2*)&g_cost[c0];
        int a0 = 0, a1 = 0;
        for (int i = 1; i < N; i++) {
            double2 cc = *(const double2*)&g_cost[i * N + c0];
            if (cc.x < vm.x) { vm.x = cc.x; a0 = i; }
            if (cc.y < vm.y) { vm.y = cc.y; a1 = i; }
        }
        v0 = vm.x; v1 = vm.y;
        s_argmin[c0] = a0; s_argmin[c1] = a1;
    }
    __syncthreads();
    if (t == 0) {
        int cnt = 0;
        for (int i = 0; i < N; i++) s_xrow[i] = -1;
        for (int jj = 0; jj < N; jj++) {
            int r = s_argmin[jj];
            if (!s_way[r]) { s_way[r] = 1; s_p[jj] = r; s_xrow[r] = jj; }
            else           { s_p[jj] = -1; }
        }
        for (int i = 0; i < N; i++)
            if (!s_way[i]) s_list[0][cnt++] = i;
        if (cnt == 0) { s_arr_done = 1; s_final_sel = 1; s_final_cnt = 0; }
        else          { s_arr_done = 0; s_cur_i = s_list[0][0]; }
        s_argmin[0] = cnt;                 // stash count
    }
    __syncthreads();

    int pb = 0;

    // ---------------------------------------------------------------
    // Phase 1b: reduction transfer (lapjv). For each CR-matched row i
    // (matched to j1): v[j1] -= min_{j != j1} (c[i][j] - v[j]).
    // v only decreases; matched column's v untouched while matched =>
    // row-min property (nonneg Dijkstra weights) holds afterwards.
    // ---------------------------------------------------------------
    for (int i = 0; i < N; i++) {
        const int j1 = s_xrow[i];          // broadcast LDS; uniform branch
        if (j1 < 0) continue;
        double2 cc = *(const double2*)&g_cost[i * N + c0];
        ull k0 = (c0 == j1) ? KEY_INF : mono_key(__dsub_rn(cc.x, v0));
        ull k1 = (c1 == j1) ? KEY_INF : mono_key(__dsub_rn(cc.y, v1));
        ull kl; int cl;
        if (k1 < k0) { kl = k1; cl = c1; } else { kl = k0; cl = c0; }
        ull bk, bp;
        block_argmin(kl, (ull)(unsigned)cl, s_slots[pb], bk, bp); pb ^= 1;
        const double m = inv_mono_key(bk);
        if (c0 == j1) v0 = __dsub_rn(v0, m);
        if (c1 == j1) v1 = __dsub_rn(v1, m);
    }
    __syncthreads();

    // ---------------------------------------------------------------
    // Phase 1c: augmenting row reduction (LAPJV), two sweeps + cap.
    // ---------------------------------------------------------------
    {
        int kidx = 1, cntIn = s_argmin[0], cntOut = 0;
        int insel = 0, outsel = 1, sweep = 0, iters = 0;

        while (true) {
            if (s_arr_done) break;
            const int i = s_cur_i;
            double2 cc = *(const double2*)&g_cost[i * N + c0];
            ull k0 = mono_key(__dsub_rn(cc.x, v0));
            ull k1 = mono_key(__dsub_rn(cc.y, v1));

            ull kl; int cl;
            if (k1 < k0) { kl = k1; cl = c1; } else { kl = k0; cl = c0; }
            ull kmin, p1u;
            block_argmin(kl, (ull)(unsigned)cl, s_slots[pb], kmin, p1u); pb ^= 1;
            const int j1 = (int)(unsigned)p1u;

            ull e0 = (c0 == j1) ? KEY_INF : k0;
            ull e1 = (c1 == j1) ? KEY_INF : k1;
            if (e1 < e0) { kl = e1; cl = c1; } else { kl = e0; cl = c0; }
            ull ksub, p2u;
            block_argmin(kl, (ull)(unsigned)cl, s_slots[pb], ksub, p2u); pb ^= 1;
            const int j2 = (int)(unsigned)p2u;

            const bool strict = (kmin < ksub);
            if (strict) {
                double dv = __dsub_rn(inv_mono_key(ksub), inv_mono_key(kmin));
                if      (j1 == c0) v0 = __dsub_rn(v0, dv);
                else if (j1 == c1) v1 = __dsub_rn(v1, dv);
            }
            if (t == 0) {
                int jf = j1;
                if (!strict && s_p[j1] >= 0) jf = j2;
                int i0 = s_p[jf];
                s_p[jf] = i;
                iters++;
                int nexti = -1;
                if (i0 >= 0 && strict) {
                    nexti = i0;                         // reprocess displaced row
                } else {
                    if (i0 >= 0) s_list[outsel][cntOut++] = i0;
                    while (true) {
                        if (kidx < cntIn) { nexti = s_list[insel][kidx++]; break; }
                        if (sweep == 0) {
                            sweep = 1; insel ^= 1; outsel ^= 1;
                            cntIn = cntOut; cntOut = 0; kidx = 0;
                            continue;
                        }
                        break;
                    }
                }
                if (nexti >= 0 && iters >= ARR_CAP) {   // safety dump
                    s_list[outsel][cntOut++] = nexti;
                    while (kidx < cntIn) s_list[outsel][cntOut++] = s_list[insel][kidx++];
                    nexti = -1;
                }
                if (nexti < 0) { s_arr_done = 1; s_final_sel = outsel; s_final_cnt = cntOut; }
                else s_cur_i = nexti;
            }
            __syncthreads();
        }
    }

    // Rebuild row duals from matched edges; free rows get u = 0.
    s_u[c0] = 0.0; s_u[c1] = 0.0;
    __syncthreads();
    {
        int r0 = s_p[c0]; if (r0 >= 0) s_u[r0] = __dsub_rn(g_cost[r0 * N + c0], v0);
        int r1 = s_p[c1]; if (r1 >= 0) s_u[r1] = __dsub_rn(g_cost[r1 * N + c1], v1);
    }
    __syncthreads();
    const int fsel = s_final_sel;
    const int fcnt = s_final_cnt;

    // ---------------------------------------------------------------
    // Phase 1d: shortest augmenting paths. Absolute distances (kept as
    // monotone integer keys in registers), duals frozen per search,
    // p[col] cached in registers and shipped in the argmin payload.
    // One barrier per Dijkstra step.
    // ---------------------------------------------------------------
    for (int f = 0; f < fcnt; f++) {
        const int iFree = s_list[fsel][f];

        ull  dk0 = KEY_INF, dk1 = KEY_INF;   // dist as monotone keys
        int  way0 = -1, way1 = -1;
        bool used0 = false, used1 = false;
        const int p0 = s_p[c0], p1 = s_p[c1];   // constant during search
        const ull pay0 = ((ull)(unsigned)(p0 + 1) << 32) | (unsigned)c0;
        const ull pay1 = ((ull)(unsigned)(p1 + 1) << 32) | (unsigned)c1;

        double dJ0 = 0.0;
        int    j0  = -1;
        int    i0  = iFree;
        double u0  = s_u[i0];
        double2 cc = *(const double2*)&g_cost[i0 * N + c0];

        while (true) {
            const double sA = __dsub_rn(u0, dJ0);    // cand = c - (sA + v)
            if (!used0) {
                ull ck = mono_key(__dsub_rn(cc.x, __dadd_rn(sA, v0)));
                if (ck < dk0) { dk0 = ck; way0 = j0; }
            }
            if (!used1) {
                ull ck = mono_key(__dsub_rn(cc.y, __dadd_rn(sA, v1)));
                if (ck < dk1) { dk1 = ck; way1 = j0; }
            }
            ull k0 = used0 ? KEY_INF : dk0;
            ull k1 = used1 ? KEY_INF : dk1;
            ull kl, pl;
            if (k1 < k0) { kl = k1; pl = pay1; } else { kl = k0; pl = pay0; }
            ull bk, bp;
            block_argmin(kl, pl, s_slots[pb], bk, bp); pb ^= 1;

            dJ0 = inv_mono_key(bk);
            const int j1  = (int)(unsigned)bp;
            const int pj1 = (int)(unsigned)(bp >> 32) - 1;
            if      (j1 == c0) { used0 = true; s_way[c0] = way0; }
            else if (j1 == c1) { used1 = true; s_way[c1] = way1; }
            j0 = j1;
            if (pj1 < 0) break;            // reached a free column
            i0 = pj1;
            u0 = s_u[i0];
            cc = *(const double2*)&g_cost[i0 * N + c0];
        }
        __syncthreads();                   // s_way complete; pre-augment snapshot

        const double distF = dJ0;
        if (used0) {
            double dd = __dsub_rn(distF, inv_mono_key(dk0));
            v0 = __dsub_rn(v0, dd);
            if (p0 >= 0) s_u[p0] = __dadd_rn(s_u[p0], dd);
        }
        if (used1) {
            double dd = __dsub_rn(distF, inv_mono_key(dk1));
            v1 = __dsub_rn(v1, dd);
            if (p1 >= 0) s_u[p1] = __dadd_rn(s_u[p1], dd);
        }
        if (t == 0) s_u[iFree] = __dadd_rn(s_u[iFree], distF);
        __syncthreads();                   // duals done before p changes

        if (t == 0) {                      // augment along parent chain
            int jc = j0;
            while (true) {
                int jp = s_way[jc];
                s_p[jc] = (jp < 0) ? iFree : s_p[jp];
                if (jp < 0) break;
                jc = jp;
            }
        }
        __syncthreads();
    }

    // ---------------------------------------------------------------
    // Phase 2: loss = 0.5 * sum_j || dgm[p[j]] - dgm_x[j] ||^2
    // ---------------------------------------------------------------
    {
        const int r0 = s_p[c0], r1 = s_p[c1];
        double db = (double)dgm[2 * r0]     - (double)dgm_x[2 * c0];
        double dd = (double)dgm[2 * r0 + 1] - (double)dgm_x[2 * c0 + 1];
        double acc = db * db + dd * dd;
        db = (double)dgm[2 * r1]     - (double)dgm_x[2 * c1];
        dd = (double)dgm[2 * r1 + 1] - (double)dgm_x[2 * c1 + 1];
        acc += db * db + dd * dd;

        #pragma unroll
        for (int off = 16; off > 0; off >>= 1)
            acc += __shfl_down_sync(FULLMASK, acc, off);
        if ((t & 31) == 0) s_red[w] = acc;
        __syncthreads();
        if (t < NW) {
            acc = s_red[t];
            #pragma unroll
            for (int off = NW / 2; off > 0; off >>= 1)
                acc += __shfl_down_sync(0x000000ffu, acc, off);
            if (t == 0) out[0] = (float)(0.5 * acc);
        }
    }
}

extern "C" void kernel_launch(void* const* d_in, const int* in_sizes, int n_in,
                              void* d_out, int out_size)
{
    const float* dgm   = (const float*)d_in[0];
    const float* dgm_x = (const float*)d_in[1];
    float* out = (float*)d_out;
    tofu_lap_kernel<<<1, NT>>>(dgm, dgm_x, out);
}

// round 9
// speedup vs baseline: 4.9016x; 1.4969x over previous
#include <cuda_runtime.h>
#include <math_constants.h>

#define N   512
#define NT  256
#define NW  (NT / 32)
#define FULLMASK 0xffffffffu
#define ARR_CAP (3 * N)

typedef long long ll;
typedef unsigned long long ull;

#define LL_INF 0x7fffffffffffffffLL
#define SIGNF  0x8000000000000000ULL
// 2^50 fixed-point scale: quantization 2^-51 per entry << optimum margin.
#define SCALE_D 1125899906842624.0

// 512x512 int64 cost matrix (2 MB) — static device scratch (no allocs).
__device__ ll g_icost[N * N];

__device__ __forceinline__ ull bias(ll x) { return (ull)x ^ SIGNF; }
__device__ __forceinline__ ll  unbias(ull k) { return (ll)(k ^ SIGNF); }

// Block-wide exact (min int64 key, payload). All NT threads call, uniform.
// One __syncthreads inside; caller double-buffers `slots`.
__device__ __forceinline__ void block_argmin(ll key, ull payload, ulonglong2* slots,
                                             ll& bk, ull& bpay)
{
    const int lane = threadIdx.x & 31;
    const int w    = threadIdx.x >> 5;
    ull bkey = bias(key);
    unsigned hi  = (unsigned)(bkey >> 32);
    unsigned lo  = (unsigned)bkey;
    unsigned whi = __reduce_min_sync(FULLMASK, hi);
    unsigned wlo = __reduce_min_sync(FULLMASK, (hi == whi) ? lo : 0xffffffffu);
    unsigned msk = __ballot_sync(FULLMASK, (hi == whi) && (lo == wlo));
    if (lane == __ffs(msk) - 1)
        slots[w] = make_ulonglong2(bkey, payload);
    __syncthreads();
    ulonglong2 a0 = slots[0], a1 = slots[1], a2 = slots[2], a3 = slots[3];
    ulonglong2 a4 = slots[4], a5 = slots[5], a6 = slots[6], a7 = slots[7];
    if (a4.x < a0.x) a0 = a4;
    if (a5.x < a1.x) a1 = a5;
    if (a6.x < a2.x) a2 = a6;
    if (a7.x < a3.x) a3 = a7;
    if (a2.x < a0.x) a0 = a2;
    if (a3.x < a1.x) a1 = a3;
    if (a1.x < a0.x) a0 = a1;
    bk   = unbias(a0.x);
    bpay = a0.y;
}

__global__ void __launch_bounds__(NT, 1)
tofu_lap_kernel(const float* __restrict__ dgm,
                const float* __restrict__ dgm_x,
                float* __restrict__ out)
{
    const int t  = threadIdx.x;       // owns columns c0 = 2t, c1 = 2t+1
    const int c0 = 2 * t, c1 = 2 * t + 1;
    const int w  = t >> 5;
    const int lane = t & 31;

    __shared__ ll         s_u[N];          // row duals (int64)
    __shared__ int        s_p[N];          // col -> matched row, -1 if free
    __shared__ int        s_way[N];        // Dijkstra parents (temp: CR row flags)
    __shared__ int        s_xrow[N];       // row -> matched col, -1 (for RT)
    __shared__ int        s_argmin[N];
    __shared__ int        s_list[2][N];    // ARR ping-pong / final free-row list
    __shared__ ulonglong2 s_slots[2][NW];  // (biased key, payload) double-buffered
    __shared__ ll         s_uslt[2][NW];   // shipped u of candidate
    __shared__ double     s_red[NW];

    // ---------------------------------------------------------------
    // Phase 0: fp64 cost (numpy-faithful: plain mul/add, IEEE sqrt),
    // then exact-enough fixed-point quantization to int64.
    // ---------------------------------------------------------------
    {
        const double xb0 = (double)dgm_x[2 * c0], xd0 = (double)dgm_x[2 * c0 + 1];
        const double xb1 = (double)dgm_x[2 * c1], xd1 = (double)dgm_x[2 * c1 + 1];
        for (int i = 0; i < N; i++) {
            const double b = (double)dgm[2 * i], d = (double)dgm[2 * i + 1];
            double db0 = __dsub_rn(b, xb0), dd0 = __dsub_rn(d, xd0);
            double db1 = __dsub_rn(b, xb1), dd1 = __dsub_rn(d, xd1);
            double e0 = sqrt(__dadd_rn(__dmul_rn(db0, db0), __dmul_rn(dd0, dd0)));
            double e1 = sqrt(__dadd_rn(__dmul_rn(db1, db1), __dmul_rn(dd1, dd1)));
            longlong2 cc;
            cc.x = __double2ll_rn(e0 * SCALE_D);
            cc.y = __double2ll_rn(e1 * SCALE_D);
            *(longlong2*)&g_icost[i * N + c0] = cc;
        }
        s_way[c0] = 0; s_way[c1] = 0;      // temp: row-claimed flags for CR
    }
    __syncthreads();

    // ---------------------------------------------------------------
    // Phase 1a: column reduction (int64). v[j] in registers.
    // ---------------------------------------------------------------
    ll v0, v1;
    {
        longlong2 vm = *(const longlong2*)&g_icost[c0];
        int a0 = 0, a1 = 0;
        for (int i = 1; i < N; i++) {
            longlong2 cc = *(const longlong2*)&g_icost[i * N + c0];
            if (cc.x < vm.x) { vm.x = cc.x; a0 = i; }
            if (cc.y < vm.y) { vm.y = cc.y; a1 = i; }
        }
        v0 = vm.x; v1 = vm.y;
        s_argmin[c0] = a0; s_argmin[c1] = a1;
    }
    __syncthreads();
    if (t == 0) {
        int cnt = 0;
        for (int i = 0; i < N; i++) s_xrow[i] = -1;
        for (int jj = 0; jj < N; jj++) {
            int r = s_argmin[jj];
            if (!s_way[r]) { s_way[r] = 1; s_p[jj] = r; s_xrow[r] = jj; }
            else           { s_p[jj] = -1; }
        }
        for (int i = 0; i < N; i++)
            if (!s_way[i]) s_list[0][cnt++] = i;
        s_argmin[0] = cnt;
    }
    __syncthreads();
    const int cnt0 = s_argmin[0];

    int pb = 0;

    // ---------------------------------------------------------------
    // Phase 1b: reduction transfer. v[j1] -= min_{j!=j1}(c[i][j]-v[j])
    // for each CR-matched row. Next-row prefetch (addresses known).
    // ---------------------------------------------------------------
    {
        longlong2 ccn = *(const longlong2*)&g_icost[c0];
        for (int i = 0; i < N; i++) {
            longlong2 cc = ccn;
            if (i + 1 < N) ccn = *(const longlong2*)&g_icost[(i + 1) * N + c0];
            const int j1 = s_xrow[i];      // broadcast LDS; uniform branch
            if (j1 < 0) continue;
            ll k0 = (c0 == j1) ? LL_INF : (cc.x - v0);
            ll k1 = (c1 == j1) ? LL_INF : (cc.y - v1);
            ll kl = (k1 < k0) ? k1 : k0;
            ll bk; ull bp;
            block_argmin(kl, 0, s_slots[pb], bk, bp); pb ^= 1;
            if (c0 == j1) v0 -= bk;
            if (c1 == j1) v1 -= bk;
        }
    }
    __syncthreads();

    // ---------------------------------------------------------------
    // Phase 1c: augmenting row reduction. Driver state fully replicated
    // across threads (uniform); only s_p / s_list writes are t0's.
    // ---------------------------------------------------------------
    int fsel, fcnt;
    {
        int p0r = s_p[c0], p1r = s_p[c1];   // register mirrors of own cols
        int kidx = 1, cntIn = cnt0, cntOut = 0;
        int insel = 0, outsel = 1, sweep = 0, iters = 0;

        if (cntIn == 0) { fsel = 1; fcnt = 0; }
        else {
            int i = s_list[0][0];
            longlong2 cc = *(const longlong2*)&g_icost[i * N + c0];
            while (true) {
                ll k0 = cc.x - v0;
                ll k1 = cc.y - v1;
                ull pay0 = ((ull)(unsigned)(p0r + 1) << 32) | (unsigned)c0;
                ull pay1 = ((ull)(unsigned)(p1r + 1) << 32) | (unsigned)c1;
                ll kl; ull pl;
                if (k1 < k0) { kl = k1; pl = pay1; } else { kl = k0; pl = pay0; }
                ll kmin; ull p1u;
                block_argmin(kl, pl, s_slots[pb], kmin, p1u); pb ^= 1;
                const int j1   = (int)(unsigned)p1u;
                const int p_j1 = (int)(unsigned)(p1u >> 32) - 1;

                // speculative: displaced-row cc (used when strict && p_j1>=0)
                longlong2 ccD;
                {
                    int pr = (p_j1 >= 0) ? p_j1 : 0;
                    ccD = *(const longlong2*)&g_icost[pr * N + c0];
                }

                ll e0 = (c0 == j1) ? LL_INF : k0;
                ll e1 = (c1 == j1) ? LL_INF : k1;
                if (e1 < e0) { kl = e1; pl = pay1; } else { kl = e0; pl = pay0; }
                ll ksub; ull p2u;
                block_argmin(kl, pl, s_slots[pb], ksub, p2u); pb ^= 1;
                const int j2   = (int)(unsigned)p2u;
                const int p_j2 = (int)(unsigned)(p2u >> 32) - 1;

                const bool strict = (kmin < ksub);
                if (strict) {
                    ll dv = ksub - kmin;
                    if      (j1 == c0) v0 -= dv;
                    else if (j1 == c1) v1 -= dv;
                }
                // uniform driver
                int jf = j1, i0;
                if (!strict && p_j1 >= 0) { jf = j2; i0 = p_j2; }
                else                      { i0 = p_j1; }
                if (t == 0) s_p[jf] = i;
                if (jf == c0) p0r = i;
                if (jf == c1) p1r = i;
                iters++;

                int nexti = -1;
                bool fromDisp = false;
                if (i0 >= 0 && strict) { nexti = i0; fromDisp = true; }
                else {
                    if (i0 >= 0) { if (t == 0) s_list[outsel][cntOut] = i0; cntOut++; }
                    while (true) {
                        if (kidx < cntIn) { nexti = s_list[insel][kidx]; kidx++; break; }
                        if (sweep == 0) {
                            sweep = 1;
                            int tmp = insel; insel = outsel; outsel = tmp;
                            cntIn = cntOut; cntOut = 0; kidx = 0;
                            __syncthreads();   // t0's list writes -> visible
                            continue;
                        }
                        break;
                    }
                }
                if (nexti >= 0 && iters >= ARR_CAP) {   // safety dump (uniform count)
                    if (t == 0) {
                        int o = cntOut;
                        s_list[outsel][o++] = nexti;
                        for (int q = kidx; q < cntIn; q++) s_list[outsel][o++] = s_list[insel][q];
                    }
                    cntOut += 1 + (cntIn - kidx);
                    nexti = -1;
                }
                if (nexti < 0) { fsel = outsel; fcnt = cntOut; break; }
                i = nexti;
                if (fromDisp) cc = ccD;
                else          cc = *(const longlong2*)&g_icost[i * N + c0];
            }
        }
    }
    __syncthreads();                       // s_p / s_list writes visible

    // Rebuild row duals from matched edges; free rows get u = 0.
    s_u[c0] = 0; s_u[c1] = 0;
    __syncthreads();
    {
        int r0 = s_p[c0]; if (r0 >= 0) s_u[r0] = g_icost[r0 * N + c0] - v0;
        int r1 = s_p[c1]; if (r1 >= 0) s_u[r1] = g_icost[r1 * N + c1] - v1;
    }
    __syncthreads();

    // ---------------------------------------------------------------
    // Phase 1d: shortest augmenting paths, int64 absolute distances.
    // Per step: 1 barrier; candidate u shipped in slots; speculative
    // prefetch of all 8 warp-candidate rows; winner row by reg select.
    // ---------------------------------------------------------------
    for (int f = 0; f < fcnt; f++) {
        const int iFree = s_list[fsel][f];

        ll   dk0 = LL_INF, dk1 = LL_INF;    // absolute dists
        int  way0 = -1, way1 = -1;
        bool used0 = false, used1 = false;
        const int p0 = s_p[c0], p1 = s_p[c1];        // frozen during search
        const ll  up0 = (p0 >= 0) ? s_u[p0] : 0;
        const ll  up1 = (p1 >= 0) ? s_u[p1] : 0;
        const ull pay0 = ((ull)(unsigned)(p0 + 1) << 32) | (unsigned)c0;
        const ull pay1 = ((ull)(unsigned)(p1 + 1) << 32) | (unsigned)c1;

        int  j0 = -1;
        ll   q  = s_u[iFree];               // q = u[i0] - dist[j0]; dist=0 at root
        ll   distF;
        longlong2 cc = *(const longlong2*)&g_icost[iFree * N + c0];

        while (true) {
            if (!used0) {
                ll cand = (cc.x - v0) - q;
                if (cand < dk0) { dk0 = cand; way0 = j0; }
            }
            if (!used1) {
                ll cand = (cc.y - v1) - q;
                if (cand < dk1) { dk1 = cand; way1 = j0; }
            }
            ll k0 = used0 ? LL_INF : dk0;
            ll k1 = used1 ? LL_INF : dk1;
            ll kl; ull pl; ll ul;
            if (k1 < k0) { kl = k1; pl = pay1; ul = up1; }
            else         { kl = k0; pl = pay0; ul = up0; }

            // warp argmin on biased key; winner lane publishes (key,pay,u)
            ull bkey = bias(kl);
            unsigned hi  = (unsigned)(bkey >> 32);
            unsigned lo  = (unsigned)bkey;
            unsigned whi = __reduce_min_sync(FULLMASK, hi);
            unsigned wlo = __reduce_min_sync(FULLMASK, (hi == whi) ? lo : 0xffffffffu);
            unsigned msk = __ballot_sync(FULLMASK, (hi == whi) && (lo == wlo));
            if (lane == __ffs(msk) - 1) {
                s_slots[pb][w] = make_ulonglong2(bkey, pl);
                s_uslt[pb][w]  = ul;
            }
            __syncthreads();                // the ONLY barrier per step

            // read slots; immediately issue speculative loads for all 8
            ull  kk[NW]; ull pp[NW]; ll uu[NW];
            #pragma unroll
            for (int m = 0; m < NW; m++) {
                ulonglong2 s = s_slots[pb][m];
                kk[m] = s.x; pp[m] = s.y;
            }
            {
                longlong2* usl = (longlong2*)s_uslt[pb];
                #pragma unroll
                for (int m = 0; m < NW / 2; m++) {
                    longlong2 uv = usl[m];
                    uu[2 * m] = uv.x; uu[2 * m + 1] = uv.y;
                }
            }
            longlong2 r[NW];
            #pragma unroll
            for (int m = 0; m < NW; m++) {
                int pm = (int)(unsigned)(pp[m] >> 32) - 1;
                int pr = (pm >= 0) ? pm : 0;
                r[m] = *(const longlong2*)&g_icost[pr * N + c0];
            }
            pb ^= 1;

            // tree over 8 (key, pay, u)
            #pragma unroll
            for (int s = NW / 2; s > 0; s >>= 1)
                #pragma unroll
                for (int m = 0; m < s; m++)
                    if (kk[m + s] < kk[m]) { kk[m] = kk[m + s]; pp[m] = pp[m + s]; uu[m] = uu[m + s]; }

            const ll  dJ  = unbias(kk[0]);
            const int j1  = (int)(unsigned)pp[0];
            const int pj1 = (int)(unsigned)(pp[0] >> 32) - 1;

            if      (j1 == c0) { used0 = true; s_way[c0] = way0; }
            else if (j1 == c1) { used1 = true; s_way[c1] = way1; }
            j0 = j1;
            if (pj1 < 0) { distF = dJ; break; }    // reached a free column

            q = uu[0] - dJ;
            const int wi = j1 >> 6;                // winner warp
            longlong2 sel = r[0];
            #pragma unroll
            for (int m = 1; m < NW; m++)
                if (wi == m) sel = r[m];
            cc = sel;
        }
        __syncthreads();                   // s_way complete; pre-augment snapshot

        // deferred dual updates (exact int adds)
        if (used0) {
            ll dd = distF - dk0;
            v0 -= dd;
            if (p0 >= 0) s_u[p0] += dd;
        }
        if (used1) {
            ll dd = distF - dk1;
            v1 -= dd;
            if (p1 >= 0) s_u[p1] += dd;
        }
        if (t == 0) s_u[iFree] += distF;
        __syncthreads();                   // duals done before p changes

        if (t == 0) {                      // augment along parent chain
            int jc = j0;
            while (true) {
                int jp = s_way[jc];
                s_p[jc] = (jp < 0) ? iFree : s_p[jp];
                if (jp < 0) break;
                jc = jp;
            }
        }
        __syncthreads();
    }

    // ---------------------------------------------------------------
    // Phase 2: loss = 0.5 * sum_j || dgm[p[j]] - dgm_x[j] ||^2 (fp64)
    // ---------------------------------------------------------------
    {
        const int r0 = s_p[c0], r1 = s_p[c1];
        double db = (double)dgm[2 * r0]     - (double)dgm_x[2 * c0];
        double dd = (double)dgm[2 * r0 + 1] - (double)dgm_x[2 * c0 + 1];
        double acc = db * db + dd * dd;
        db = (double)dgm[2 * r1]     - (double)dgm_x[2 * c1];
        dd = (double)dgm[2 * r1 + 1] - (double)dgm_x[2 * c1 + 1];
        acc += db * db + dd * dd;

        #pragma unroll
        for (int off = 16; off > 0; off >>= 1)
            acc += __shfl_down_sync(FULLMASK, acc, off);
        if (lane == 0) s_red[w] = acc;
        __syncthreads();
        if (t < NW) {
            acc = s_red[t];
            #pragma unroll
            for (int off = NW / 2; off > 0; off >>= 1)
                acc += __shfl_down_sync(0x000000ffu, acc, off);
            if (t == 0) out[0] = (float)(0.5 * acc);
        }
    }
}

extern "C" void kernel_launch(void* const* d_in, const int* in_sizes, int n_in,
                              void* d_out, int out_size)
{
    const float* dgm   = (const float*)d_in[0];
    const float* dgm_x = (const float*)d_in[1];
    float* out = (float*)d_out;
    tofu_lap_kernel<<<1, NT>>>(dgm, dgm_x, out);
}